// round 5
// baseline (speedup 1.0000x reference)
#include <cuda_runtime.h>
#include <cstdint>

#define Bn 32
#define Cc 256
#define Gg 4
#define CG 64
#define Hh 56
#define Ww 56
#define OH 28
#define OW 28
#define Pp (OH*OW)          // 784
#define HWin (Hh*Ww)        // 3136
#define NOUT (Bn*Cc*Pp)     // 6422528
#define CNT (Bn*Pp)         // 25088 elements per channel
#define EPSBN 1e-5

// -------- scratch (device globals; no dynamic allocation) --------
__device__ unsigned long long g_packed1[Bn*Gg*HWin];   // sign(x) packed, 64 ch/word
__device__ unsigned long long g_packed2[Bn*Pp*4];      // sign(out1) packed
__device__ unsigned long long g_pw1[Cc*9];             // packed w1 signs [oc][tap]
__device__ unsigned long long g_pw2[Cc*4];             // packed w2 signs [oc][word]
__device__ float g_pool[NOUT];
__device__ short g_y1[NOUT];
__device__ short g_y2[NOUT];
__device__ float g_a1[Cc], g_b1[Cc], g_a2[Cc], g_b2[Cc];
// integer BN accumulators (exact, deterministic)
__device__ int g_sum1[Cc], g_sum2[Cc];
__device__ unsigned long long g_sq1[Cc], g_sq2[Cc];

// -------- pack weights + zero stat accumulators --------
__global__ void pack_w_kernel(const float* __restrict__ w1, const float* __restrict__ w2) {
    int tid = blockIdx.x * blockDim.x + threadIdx.x;
    if (tid < Cc) { g_sum1[tid] = 0; g_sum2[tid] = 0; g_sq1[tid] = 0ull; g_sq2[tid] = 0ull; }
    if (tid < Cc * 9) {
        int oc = tid / 9, t = tid % 9;
        unsigned long long word = 0ull;
        #pragma unroll 8
        for (int ic = 0; ic < CG; ic++)
            if (w1[(oc * CG + ic) * 9 + t] > 0.f) word |= 1ull << ic;
        g_pw1[tid] = word;
    } else if (tid < Cc * 9 + Cc) {
        int oc = tid - Cc * 9;
        #pragma unroll
        for (int j = 0; j < 4; j++) {
            unsigned long long word = 0ull;
            #pragma unroll 8
            for (int i = 0; i < 64; i++)
                if (w2[oc * Cc + j * 64 + i] > 0.f) word |= 1ull << i;
            g_pw2[oc * 4 + j] = word;
        }
    }
}

// -------- prep: fused maxpool + sign-pack, x read ONCE through smem.
// grid (28, 4, 32) = (oh, group, n); block 512.
__global__ void __launch_bounds__(512) prep_kernel(const float* __restrict__ x) {
    __shared__ float s_x[64][171];                       // [c][r*57+iw]
    int oh = blockIdx.x, g = blockIdx.y, n = blockIdx.z;
    int t = threadIdx.x;
    const float* xb = x + (size_t)(n * Cc + g * 64) * HWin;

    for (int j = t; j < 64 * 168; j += 512) {
        int c = j / 168, rem = j % 168, r = rem / 56, iw = rem % 56;
        int ih = 2 * oh - 1 + r;                         // never >= 56
        s_x[c][r * 57 + iw] = (ih >= 0) ? xb[(size_t)c * HWin + ih * 56 + iw] : -3.4e38f;
    }
    __syncthreads();

    // maxpool 3x3 s2 p1 for output row oh
    for (int item = t; item < 64 * 28; item += 512) {
        int c = item / 28, ow = item % 28;
        float m = -3.4e38f;
        #pragma unroll
        for (int r = 0; r < 3; r++) {
            #pragma unroll
            for (int kw = 0; kw < 3; kw++) {
                int iw = 2 * ow - 1 + kw;
                if (iw >= 0 && iw < 56) m = fmaxf(m, s_x[c][r * 57 + iw]);
            }
        }
        g_pool[(size_t)(n * Cc + g * 64 + c) * Pp + oh * 28 + ow] = m;
    }

    // pack input rows 2oh, 2oh+1 (r = 1, 2): 112 words
    for (int wi = t; wi < 112; wi += 512) {
        int r = 1 + wi / 56, iw = wi % 56;
        unsigned long long word = 0ull;
        #pragma unroll 16
        for (int c = 0; c < 64; c++)
            if (s_x[c][r * 57 + iw] > 0.f) word |= 1ull << c;
        g_packed1[(size_t)(n * Gg + g) * HWin + (2 * oh - 1 + r) * 56 + iw] = word;
    }
}

// -------- conv1: grouped 3x3 s2 p1, XNOR-popcount + fused BN stats.
// grid (196, 8); block (128,4). blockIdx.y: bits[2:1]=group, bit0=oc half.
__global__ void __launch_bounds__(512) conv1_kernel() {
    __shared__ unsigned long long s_w[32 * 9];
    __shared__ int s_sum[32], s_sq[32];
    int g    = blockIdx.y >> 1;
    int half = blockIdx.y & 1;
    int chbase = g * CG + half * 32;
    int tflat = threadIdx.y * 128 + threadIdx.x;
    for (int i = tflat; i < 32 * 9; i += 512) s_w[i] = g_pw1[chbase * 9 + i];
    if (tflat < 32) { s_sum[tflat] = 0; s_sq[tflat] = 0; }
    __syncthreads();

    int item = blockIdx.x * 128 + threadIdx.x;           // 0..25087 exact
    int n = item / Pp, p = item % Pp;
    int oh = p / OW, ow = p % OW;

    unsigned long long xw[9], msk[9];
    int nv = 0;
    #pragma unroll
    for (int tt = 0; tt < 9; tt++) {
        int kh = tt / 3, kw = tt % 3;
        int ih = 2 * oh - 1 + kh, iw = 2 * ow - 1 + kw;
        bool v = ((unsigned)ih < Hh) && ((unsigned)iw < Ww);
        xw[tt]  = v ? g_packed1[(size_t)(n * Gg + g) * HWin + ih * Ww + iw] : 0ull;
        msk[tt] = v ? ~0ull : 0ull;
        nv += v ? 1 : 0;
    }

    int base = 64 * nv;
    int ocs = threadIdx.y * 8;
    short* yp = g_y1 + (size_t)(n * Cc + chbase + ocs) * Pp + p;
    #pragma unroll
    for (int k = 0; k < 8; k++) {
        const unsigned long long* wp = s_w + (ocs + k) * 9;
        int m = 0;
        #pragma unroll
        for (int tt = 0; tt < 9; tt++)
            m += __popcll((xw[tt] ^ wp[tt]) & msk[tt]);
        int v = base - 2 * m;
        yp[(size_t)k * Pp] = (short)v;
        int ws = __reduce_add_sync(0xffffffffu, v);
        int wq = __reduce_add_sync(0xffffffffu, v * v);
        if ((threadIdx.x & 31) == 0) {
            atomicAdd(&s_sum[ocs + k], ws);
            atomicAdd(&s_sq[ocs + k], wq);
        }
    }
    __syncthreads();
    if (tflat < 32) {
        atomicAdd(&g_sum1[chbase + tflat], s_sum[tflat]);
        atomicAdd(&g_sq1[chbase + tflat], (unsigned long long)(unsigned int)s_sq[tflat]);
    }
}

// -------- finalize BN affine params from exact integer sums (1 block) --------
__global__ void bn_finalize_kernel(int which, const float* __restrict__ gamma,
                                   const float* __restrict__ beta) {
    int c = threadIdx.x;
    long long s  = which ? g_sum2[c] : g_sum1[c];
    double sq    = (double)(which ? g_sq2[c] : g_sq1[c]);
    double mu  = (double)s / (double)CNT;
    double var = sq / (double)CNT - mu * mu;
    double ai  = (double)gamma[c] / sqrt(var + EPSBN);
    if (which) { g_a2[c] = (float)ai; g_b2[c] = (float)((double)beta[c] - mu * ai); }
    else       { g_a1[c] = (float)ai; g_b1[c] = (float)((double)beta[c] - mu * ai); }
}

// -------- binarize out1 = bn1(y1)+pool into packed words --------
__global__ void bn1_fuse_kernel() {
    int n = blockIdx.x / 7;
    int p = (blockIdx.x % 7) * 128 + threadIdx.x;
    if (p >= Pp) return;
    int j = threadIdx.y;
    unsigned long long word = 0ull;
    #pragma unroll 4
    for (int c64 = 0; c64 < 64; c64++) {
        int c = j * 64 + c64;
        size_t idx = (size_t)(n * Cc + c) * Pp + p;
        float v = g_a1[c] * (float)g_y1[idx] + g_b1[c] + g_pool[idx];
        if (v > 0.f) word |= 1ull << c64;
    }
    g_packed2[(size_t)(n * Pp + p) * 4 + j] = word;
}

// -------- conv2: 1x1, K=256, XNOR-popcount + fused BN stats.
// grid (196, 8); block (128,4). blockIdx.y = 32-oc chunk.
__global__ void __launch_bounds__(512) conv2_kernel() {
    __shared__ unsigned long long s_w[32 * 4];
    __shared__ int s_sum[32], s_sq[32];
    int q = blockIdx.y;
    int chbase = q * 32;
    int tflat = threadIdx.y * 128 + threadIdx.x;
    for (int i = tflat; i < 32 * 4; i += 512) s_w[i] = g_pw2[chbase * 4 + i];
    if (tflat < 32) { s_sum[tflat] = 0; s_sq[tflat] = 0; }
    __syncthreads();

    int item = blockIdx.x * 128 + threadIdx.x;
    size_t pb = (size_t)item * 4;
    unsigned long long xa0 = g_packed2[pb + 0];
    unsigned long long xa1 = g_packed2[pb + 1];
    unsigned long long xa2 = g_packed2[pb + 2];
    unsigned long long xa3 = g_packed2[pb + 3];

    int n = item / Pp, p = item % Pp;
    int ocs = threadIdx.y * 8;
    short* yp = g_y2 + (size_t)(n * Cc + chbase + ocs) * Pp + p;
    #pragma unroll
    for (int k = 0; k < 8; k++) {
        const unsigned long long* wp = s_w + (ocs + k) * 4;
        int m = __popcll(xa0 ^ wp[0]) + __popcll(xa1 ^ wp[1])
              + __popcll(xa2 ^ wp[2]) + __popcll(xa3 ^ wp[3]);
        int v = 256 - 2 * m;
        yp[(size_t)k * Pp] = (short)v;
        int ws = __reduce_add_sync(0xffffffffu, v);
        int wq = __reduce_add_sync(0xffffffffu, v * v);
        if ((threadIdx.x & 31) == 0) {
            atomicAdd(&s_sum[ocs + k], ws);
            atomicAdd(&s_sq[ocs + k], wq);
        }
    }
    __syncthreads();
    if (tflat < 32) {
        atomicAdd(&g_sum2[chbase + tflat], s_sum[tflat]);
        atomicAdd(&g_sq2[chbase + tflat], (unsigned long long)(unsigned int)s_sq[tflat]);
    }
}

// -------- final: out = bn2(y2) + bn1(y1) + pool, vectorized x4 --------
__global__ void final_kernel(float* __restrict__ out) {
    int idx = blockIdx.x * blockDim.x + threadIdx.x;
    if (idx >= NOUT / 4) return;
    int e = idx * 4;
    int c = (e / Pp) % Cc;
    short4 y2 = *(const short4*)(g_y2 + e);
    short4 y1 = *(const short4*)(g_y1 + e);
    float4 pl = *(const float4*)(g_pool + e);
    float a2 = g_a2[c], b2 = g_b2[c];
    float a1 = g_a1[c], b1 = g_b1[c];
    float bb = b1 + b2;
    float4 r;
    r.x = a2 * (float)y2.x + a1 * (float)y1.x + bb + pl.x;
    r.y = a2 * (float)y2.y + a1 * (float)y1.y + bb + pl.y;
    r.z = a2 * (float)y2.z + a1 * (float)y1.z + bb + pl.z;
    r.w = a2 * (float)y2.w + a1 * (float)y1.w + bb + pl.w;
    *(float4*)(out + e) = r;
}

extern "C" void kernel_launch(void* const* d_in, const int* in_sizes, int n_in,
                              void* d_out, int out_size) {
    const float* x      = (const float*)d_in[0];
    const float* w1     = (const float*)d_in[1];
    const float* w2     = (const float*)d_in[2];
    const float* gamma1 = (const float*)d_in[3];
    const float* beta1  = (const float*)d_in[4];
    const float* gamma2 = (const float*)d_in[5];
    const float* beta2  = (const float*)d_in[6];
    float* out = (float*)d_out;

    pack_w_kernel<<<10, 256>>>(w1, w2);
    prep_kernel<<<dim3(28, 4, 32), 512>>>(x);
    conv1_kernel<<<dim3(196, 8), dim3(128, 4)>>>();
    bn_finalize_kernel<<<1, 256>>>(0, gamma1, beta1);
    bn1_fuse_kernel<<<Bn * 7, dim3(128, 4)>>>();
    conv2_kernel<<<dim3(196, 8), dim3(128, 4)>>>();
    bn_finalize_kernel<<<1, 256>>>(1, gamma2, beta2);
    final_kernel<<<(NOUT / 4 + 255) / 256, 256>>>(out);
}